// round 1
// baseline (speedup 1.0000x reference)
#include <cuda_runtime.h>
#include <math.h>

// Problem dims
#define Bb 64
#define Tt 512
#define Dd 1024
#define Uu 1024
#define G4 4096   // 4*U

// Scratch (allocation-free rule -> __device__ globals)
__device__ float g_xproj[(size_t)Bb * Tt * G4];   // [B*T, 4U]  512 MB
__device__ float g_h[2][Bb * Uu];                 // ping-pong hidden state
__device__ float g_c[Bb * Uu];                    // cell state

// ---------------------------------------------------------------------------
// init: zero h[0] and c
// ---------------------------------------------------------------------------
__global__ void init_kernel() {
    int i = blockIdx.x * blockDim.x + threadIdx.x;
    if (i < Bb * Uu) {
        g_h[0][i] = 0.0f;
        g_c[i]    = 0.0f;
    }
}

// ---------------------------------------------------------------------------
// x_proj = x @ Wx + b      (M=B*T=32768, N=4U=4096, K=D=1024)
// Tiled SGEMM: 128x128 block tile, BK=16, 256 threads, 8x8 microtile.
// ---------------------------------------------------------------------------
__global__ __launch_bounds__(256) void xproj_kernel(
    const float* __restrict__ x,
    const float* __restrict__ Wx,
    const float* __restrict__ bias)
{
    __shared__ float As[16][132];   // A transposed: As[k][m], padded
    __shared__ float Bs[16][128];   // Bs[k][n]

    const int m0 = blockIdx.y * 128;
    const int n0 = blockIdx.x * 128;
    const int tid = threadIdx.x;
    const int ty  = tid >> 4;       // 0..15, rows ty*8..ty*8+7
    const int tx  = tid & 15;       // 0..15, cols tx*8..tx*8+7

    float acc[8][8];
#pragma unroll
    for (int i = 0; i < 8; i++)
#pragma unroll
        for (int j = 0; j < 8; j++) acc[i][j] = 0.0f;

    const int ar = tid >> 2;            // 0..63
    const int ac = (tid & 3) * 4;       // 0,4,8,12
    const int br = tid >> 5;            // 0..7
    const int bc = (tid & 31) * 4;      // 0..124

    for (int k0 = 0; k0 < Dd; k0 += 16) {
        // load A tile (128 rows x 16 k), store transposed
        {
            float4 v0 = *(const float4*)&x[(size_t)(m0 + ar) * Dd + k0 + ac];
            As[ac + 0][ar] = v0.x; As[ac + 1][ar] = v0.y;
            As[ac + 2][ar] = v0.z; As[ac + 3][ar] = v0.w;
            float4 v1 = *(const float4*)&x[(size_t)(m0 + ar + 64) * Dd + k0 + ac];
            As[ac + 0][ar + 64] = v1.x; As[ac + 1][ar + 64] = v1.y;
            As[ac + 2][ar + 64] = v1.z; As[ac + 3][ar + 64] = v1.w;
        }
        // load B tile (16 k x 128 n)
        {
            *(float4*)&Bs[br][bc]     = *(const float4*)&Wx[(size_t)(k0 + br) * G4 + n0 + bc];
            *(float4*)&Bs[br + 8][bc] = *(const float4*)&Wx[(size_t)(k0 + br + 8) * G4 + n0 + bc];
        }
        __syncthreads();

#pragma unroll
        for (int k = 0; k < 16; k++) {
            float4 a0 = *(const float4*)&As[k][ty * 8];
            float4 a1 = *(const float4*)&As[k][ty * 8 + 4];
            float4 b0 = *(const float4*)&Bs[k][tx * 8];
            float4 b1 = *(const float4*)&Bs[k][tx * 8 + 4];
            float av[8] = {a0.x, a0.y, a0.z, a0.w, a1.x, a1.y, a1.z, a1.w};
            float bv[8] = {b0.x, b0.y, b0.z, b0.w, b1.x, b1.y, b1.z, b1.w};
#pragma unroll
            for (int i = 0; i < 8; i++)
#pragma unroll
                for (int j = 0; j < 8; j++)
                    acc[i][j] += av[i] * bv[j];
        }
        __syncthreads();
    }

    // epilogue: add bias, write x_proj
#pragma unroll
    for (int i = 0; i < 8; i++) {
        const int m = m0 + ty * 8 + i;
        float* out = &g_xproj[(size_t)m * G4 + n0 + tx * 8];
#pragma unroll
        for (int j = 0; j < 8; j++)
            out[j] = acc[i][j] + bias[n0 + tx * 8 + j];
    }
}

// ---------------------------------------------------------------------------
// One LSTM timestep, fused: z = x_proj[:,t,:] + h@Wh + b ; gates ; c,h update.
// Grid: 128 blocks, each owns an 8-wide u-slice (all 4 gates, 32 gate cols).
// GEMM: M=64 (batch), N=32 (gate cols), K=1024.
// ---------------------------------------------------------------------------
__global__ __launch_bounds__(256) void step_kernel(
    const float* __restrict__ Wh,
    const float* __restrict__ bias,
    float* __restrict__ y,
    int t)
{
    __shared__ float Hs[32][68];    // h transposed: Hs[k][b], 16B-aligned rows
    __shared__ float Ws[32][33];    // Ws[k][c], c = gate*8 + uu
    __shared__ float Zs[64][33];    // gate exchange

    const int u0  = blockIdx.x * 8;
    const int tid = threadIdx.x;
    const int ty  = tid >> 4;       // row group: rows ty*4 .. ty*4+3
    const int tx  = tid & 15;       // col group: cols tx*2, tx*2+1

    const float* __restrict__ hprev = g_h[t & 1];
    float* __restrict__ hnext = g_h[(t + 1) & 1];

    float acc[8];
#pragma unroll
    for (int i = 0; i < 8; i++) acc[i] = 0.0f;

    for (int kt = 0; kt < 32; kt++) {
        const int k0 = kt * 32;
        // load H tile: 64 b x 32 k, transposed into Hs[k][b]
#pragma unroll
        for (int it = 0; it < 2; it++) {
            int idx = tid + it * 256;
            int bb = idx >> 3, cc = idx & 7;
            float4 v = *(const float4*)&hprev[bb * Uu + k0 + cc * 4];
            Hs[cc * 4 + 0][bb] = v.x; Hs[cc * 4 + 1][bb] = v.y;
            Hs[cc * 4 + 2][bb] = v.z; Hs[cc * 4 + 3][bb] = v.w;
        }
        // load W tile: 32 k x 32 gate-cols
#pragma unroll
        for (int it = 0; it < 4; it++) {
            int idx = tid + it * 256;
            int kk = idx >> 5, cc = idx & 31;
            int gcol = (cc >> 3) * Uu + u0 + (cc & 7);
            Ws[kk][cc] = Wh[(size_t)(k0 + kk) * G4 + gcol];
        }
        __syncthreads();

#pragma unroll
        for (int k = 0; k < 32; k++) {
            float4 hv = *(const float4*)&Hs[k][ty * 4];
            float w0 = Ws[k][tx * 2];
            float w1 = Ws[k][tx * 2 + 1];
            acc[0] += hv.x * w0; acc[1] += hv.y * w0;
            acc[2] += hv.z * w0; acc[3] += hv.w * w0;
            acc[4] += hv.x * w1; acc[5] += hv.y * w1;
            acc[6] += hv.z * w1; acc[7] += hv.w * w1;
        }
        __syncthreads();
    }

    // exchange z through smem so each (b,u) thread sees all 4 gates
#pragma unroll
    for (int i = 0; i < 4; i++) {
        Zs[ty * 4 + i][tx * 2]     = acc[i];
        Zs[ty * 4 + i][tx * 2 + 1] = acc[4 + i];
    }
    __syncthreads();

    // pointwise gates: 64 b x 8 uu = 512 cells, 2 per thread
#pragma unroll
    for (int it = 0; it < 2; it++) {
        int p  = tid + it * 256;
        int bb = p >> 3;
        int uu = p & 7;
        int col = u0 + uu;

        const float* xp = &g_xproj[((size_t)bb * Tt + t) * G4];
        float zi = Zs[bb][uu]      + xp[col]           + bias[col];
        float zf = Zs[bb][8 + uu]  + xp[Uu + col]      + bias[Uu + col];
        float zg = Zs[bb][16 + uu] + xp[2 * Uu + col]  + bias[2 * Uu + col];
        float zo = Zs[bb][24 + uu] + xp[3 * Uu + col]  + bias[3 * Uu + col];

        float ig = 1.0f / (1.0f + __expf(-zi));
        float fg = 1.0f / (1.0f + __expf(-zf));
        float gg = tanhf(zg);
        float og = 1.0f / (1.0f + __expf(-zo));

        float cold = g_c[bb * Uu + col];
        float cn   = fg * cold + ig * gg;
        g_c[bb * Uu + col] = cn;
        float h = og * tanhf(cn);
        hnext[bb * Uu + col] = h;
        y[((size_t)bb * Tt + t) * Uu + col] = h;
    }
}

// ---------------------------------------------------------------------------
extern "C" void kernel_launch(void* const* d_in, const int* in_sizes, int n_in,
                              void* d_out, int out_size)
{
    const float* x   = (const float*)d_in[0];
    const float* Wx  = (const float*)d_in[1];
    const float* Wh  = (const float*)d_in[2];
    const float* b   = (const float*)d_in[3];
    float* y = (float*)d_out;

    init_kernel<<<(Bb * Uu + 255) / 256, 256>>>();

    dim3 grid_xp(G4 / 128, (Bb * Tt) / 128);
    xproj_kernel<<<grid_xp, 256>>>(x, Wx, b);

    for (int t = 0; t < Tt; t++) {
        step_kernel<<<Uu / 8, 256>>>(Wh, b, y, t);
    }
}

// round 2
// speedup vs baseline: 1.0026x; 1.0026x over previous
#include <cuda_runtime.h>
#include <math.h>

// Problem dims
#define Bb 64
#define Tt 512
#define Dd 1024
#define Uu 1024
#define G4 4096   // 4*U

// Scratch (allocation-free rule -> __device__ globals)
__device__ float g_xproj[(size_t)Bb * Tt * G4];   // [B*T, 4U]  512 MB
__device__ float g_h[2][Bb * Uu];                 // ping-pong hidden state
__device__ float g_c[Bb * Uu];                    // cell state

// ---------------------------------------------------------------------------
// init: zero h[0] and c
// ---------------------------------------------------------------------------
__global__ void init_kernel() {
    int i = blockIdx.x * blockDim.x + threadIdx.x;
    if (i < Bb * Uu) {
        g_h[0][i] = 0.0f;
        g_c[i]    = 0.0f;
    }
}

// ---------------------------------------------------------------------------
// x_proj = x @ Wx + b      (M=B*T=32768, N=4U=4096, K=D=1024)
// Tiled SGEMM: 128x128 block tile, BK=16, 256 threads, 8x8 microtile.
// ---------------------------------------------------------------------------
__global__ __launch_bounds__(256) void xproj_kernel(
    const float* __restrict__ x,
    const float* __restrict__ Wx,
    const float* __restrict__ bias)
{
    __shared__ float As[16][132];   // A transposed: As[k][m], padded
    __shared__ float Bs[16][128];   // Bs[k][n]

    const int m0 = blockIdx.y * 128;
    const int n0 = blockIdx.x * 128;
    const int tid = threadIdx.x;
    const int ty  = tid >> 4;       // 0..15, rows ty*8..ty*8+7
    const int tx  = tid & 15;       // 0..15, cols tx*8..tx*8+7

    float acc[8][8];
#pragma unroll
    for (int i = 0; i < 8; i++)
#pragma unroll
        for (int j = 0; j < 8; j++) acc[i][j] = 0.0f;

    const int ar = tid >> 2;            // 0..63
    const int ac = (tid & 3) * 4;       // 0,4,8,12
    const int br = tid >> 5;            // 0..7
    const int bc = (tid & 31) * 4;      // 0..124

    for (int k0 = 0; k0 < Dd; k0 += 16) {
        // load A tile (128 rows x 16 k), store transposed
        {
            float4 v0 = *(const float4*)&x[(size_t)(m0 + ar) * Dd + k0 + ac];
            As[ac + 0][ar] = v0.x; As[ac + 1][ar] = v0.y;
            As[ac + 2][ar] = v0.z; As[ac + 3][ar] = v0.w;
            float4 v1 = *(const float4*)&x[(size_t)(m0 + ar + 64) * Dd + k0 + ac];
            As[ac + 0][ar + 64] = v1.x; As[ac + 1][ar + 64] = v1.y;
            As[ac + 2][ar + 64] = v1.z; As[ac + 3][ar + 64] = v1.w;
        }
        // load B tile (16 k x 128 n)
        {
            *(float4*)&Bs[br][bc]     = *(const float4*)&Wx[(size_t)(k0 + br) * G4 + n0 + bc];
            *(float4*)&Bs[br + 8][bc] = *(const float4*)&Wx[(size_t)(k0 + br + 8) * G4 + n0 + bc];
        }
        __syncthreads();

#pragma unroll
        for (int k = 0; k < 16; k++) {
            float4 a0 = *(const float4*)&As[k][ty * 8];
            float4 a1 = *(const float4*)&As[k][ty * 8 + 4];
            float4 b0 = *(const float4*)&Bs[k][tx * 8];
            float4 b1 = *(const float4*)&Bs[k][tx * 8 + 4];
            float av[8] = {a0.x, a0.y, a0.z, a0.w, a1.x, a1.y, a1.z, a1.w};
            float bv[8] = {b0.x, b0.y, b0.z, b0.w, b1.x, b1.y, b1.z, b1.w};
#pragma unroll
            for (int i = 0; i < 8; i++)
#pragma unroll
                for (int j = 0; j < 8; j++)
                    acc[i][j] += av[i] * bv[j];
        }
        __syncthreads();
    }

    // epilogue: add bias, write x_proj
#pragma unroll
    for (int i = 0; i < 8; i++) {
        const int m = m0 + ty * 8 + i;
        float* out = &g_xproj[(size_t)m * G4 + n0 + tx * 8];
#pragma unroll
        for (int j = 0; j < 8; j++)
            out[j] = acc[i][j] + bias[n0 + tx * 8 + j];
    }
}

// ---------------------------------------------------------------------------
// One LSTM timestep, fused: z = x_proj[:,t,:] + h@Wh + b ; gates ; c,h update.
// Grid: 128 blocks, each owns an 8-wide u-slice (all 4 gates, 32 gate cols).
// GEMM: M=64 (batch), N=32 (gate cols), K=1024.
// ---------------------------------------------------------------------------
__global__ __launch_bounds__(256) void step_kernel(
    const float* __restrict__ Wh,
    const float* __restrict__ bias,
    float* __restrict__ y,
    int t)
{
    __shared__ float Hs[32][68];    // h transposed: Hs[k][b], 16B-aligned rows
    __shared__ float Ws[32][33];    // Ws[k][c], c = gate*8 + uu
    __shared__ float Zs[64][33];    // gate exchange

    const int u0  = blockIdx.x * 8;
    const int tid = threadIdx.x;
    const int ty  = tid >> 4;       // row group: rows ty*4 .. ty*4+3
    const int tx  = tid & 15;       // col group: cols tx*2, tx*2+1

    const float* __restrict__ hprev = g_h[t & 1];
    float* __restrict__ hnext = g_h[(t + 1) & 1];

    float acc[8];
#pragma unroll
    for (int i = 0; i < 8; i++) acc[i] = 0.0f;

    for (int kt = 0; kt < 32; kt++) {
        const int k0 = kt * 32;
        // load H tile: 64 b x 32 k, transposed into Hs[k][b]
#pragma unroll
        for (int it = 0; it < 2; it++) {
            int idx = tid + it * 256;
            int bb = idx >> 3, cc = idx & 7;
            float4 v = *(const float4*)&hprev[bb * Uu + k0 + cc * 4];
            Hs[cc * 4 + 0][bb] = v.x; Hs[cc * 4 + 1][bb] = v.y;
            Hs[cc * 4 + 2][bb] = v.z; Hs[cc * 4 + 3][bb] = v.w;
        }
        // load W tile: 32 k x 32 gate-cols
#pragma unroll
        for (int it = 0; it < 4; it++) {
            int idx = tid + it * 256;
            int kk = idx >> 5, cc = idx & 31;
            int gcol = (cc >> 3) * Uu + u0 + (cc & 7);
            Ws[kk][cc] = Wh[(size_t)(k0 + kk) * G4 + gcol];
        }
        __syncthreads();

#pragma unroll
        for (int k = 0; k < 32; k++) {
            float4 hv = *(const float4*)&Hs[k][ty * 4];
            float w0 = Ws[k][tx * 2];
            float w1 = Ws[k][tx * 2 + 1];
            acc[0] += hv.x * w0; acc[1] += hv.y * w0;
            acc[2] += hv.z * w0; acc[3] += hv.w * w0;
            acc[4] += hv.x * w1; acc[5] += hv.y * w1;
            acc[6] += hv.z * w1; acc[7] += hv.w * w1;
        }
        __syncthreads();
    }

    // exchange z through smem so each (b,u) thread sees all 4 gates
#pragma unroll
    for (int i = 0; i < 4; i++) {
        Zs[ty * 4 + i][tx * 2]     = acc[i];
        Zs[ty * 4 + i][tx * 2 + 1] = acc[4 + i];
    }
    __syncthreads();

    // pointwise gates: 64 b x 8 uu = 512 cells, 2 per thread
#pragma unroll
    for (int it = 0; it < 2; it++) {
        int p  = tid + it * 256;
        int bb = p >> 3;
        int uu = p & 7;
        int col = u0 + uu;

        const float* xp = &g_xproj[((size_t)bb * Tt + t) * G4];
        float zi = Zs[bb][uu]      + xp[col]           + bias[col];
        float zf = Zs[bb][8 + uu]  + xp[Uu + col]      + bias[Uu + col];
        float zg = Zs[bb][16 + uu] + xp[2 * Uu + col]  + bias[2 * Uu + col];
        float zo = Zs[bb][24 + uu] + xp[3 * Uu + col]  + bias[3 * Uu + col];

        float ig = 1.0f / (1.0f + __expf(-zi));
        float fg = 1.0f / (1.0f + __expf(-zf));
        float gg = tanhf(zg);
        float og = 1.0f / (1.0f + __expf(-zo));

        float cold = g_c[bb * Uu + col];
        float cn   = fg * cold + ig * gg;
        g_c[bb * Uu + col] = cn;
        float h = og * tanhf(cn);
        hnext[bb * Uu + col] = h;
        y[((size_t)bb * Tt + t) * Uu + col] = h;
    }
}

// ---------------------------------------------------------------------------
extern "C" void kernel_launch(void* const* d_in, const int* in_sizes, int n_in,
                              void* d_out, int out_size)
{
    const float* x   = (const float*)d_in[0];
    const float* Wx  = (const float*)d_in[1];
    const float* Wh  = (const float*)d_in[2];
    const float* b   = (const float*)d_in[3];
    float* y = (float*)d_out;

    init_kernel<<<(Bb * Uu + 255) / 256, 256>>>();

    dim3 grid_xp(G4 / 128, (Bb * Tt) / 128);
    xproj_kernel<<<grid_xp, 256>>>(x, Wx, b);

    for (int t = 0; t < Tt; t++) {
        step_kernel<<<Uu / 8, 256>>>(Wh, b, y, t);
    }
}

// round 4
// speedup vs baseline: 2.3324x; 2.3264x over previous
#include <cuda_runtime.h>
#include <cuda_bf16.h>
#include <cstdint>

// dims: B=64, T=512, D=U=1024, 4U=4096
#define Kd 1024
#define NT 4096

// ---------------- scratch (__device__ globals) -----------------------------
__device__ __align__(16) __nv_bfloat16 g_xh[(size_t)32768 * 1024];
__device__ __align__(16) __nv_bfloat16 g_xl[(size_t)32768 * 1024];
__device__ __align__(16) __nv_bfloat16 g_wxh[(size_t)4096 * 1024];
__device__ __align__(16) __nv_bfloat16 g_wxl[(size_t)4096 * 1024];
__device__ __align__(16) __nv_bfloat16 g_whh[(size_t)4096 * 1024];
__device__ __align__(16) __nv_bfloat16 g_whl[(size_t)4096 * 1024];
__device__ __align__(16) __nv_bfloat16 g_hh[2][64 * 1024];
__device__ __align__(16) __nv_bfloat16 g_hl[2][64 * 1024];
__device__ float g_c[64 * 1024];                       // [b][u]
__device__ float g_xproj[(size_t)512 * 4096 * 64];     // [t][p][b], bias folded

// ---------------- helpers --------------------------------------------------
__device__ __forceinline__ uint32_t smem_u32(const void* p) {
    uint32_t a;
    asm("{ .reg .u64 t; cvta.to.shared.u64 t, %1; cvt.u32.u64 %0, t; }" : "=r"(a) : "l"(p));
    return a;
}
__device__ __forceinline__ void cp16(uint32_t saddr, const void* g) {
    asm volatile("cp.async.cg.shared.global [%0], [%1], 16;" :: "r"(saddr), "l"(g) : "memory");
}
#define CP_COMMIT() asm volatile("cp.async.commit_group;" ::: "memory")
#define CP_WAIT1()  asm volatile("cp.async.wait_group 1;" ::: "memory")
#define CP_WAIT0()  asm volatile("cp.async.wait_group 0;" ::: "memory")

__device__ __forceinline__ void ldsm4(uint32_t* r, uint32_t addr) {
    asm volatile("ldmatrix.sync.aligned.m8n8.x4.shared.b16 {%0,%1,%2,%3}, [%4];"
        : "=r"(r[0]), "=r"(r[1]), "=r"(r[2]), "=r"(r[3]) : "r"(addr));
}
__device__ __forceinline__ void mma_bf16(float* c, const uint32_t* a, uint32_t b0, uint32_t b1) {
    asm volatile("mma.sync.aligned.m16n8k16.row.col.f32.bf16.bf16.f32 "
        "{%0,%1,%2,%3}, {%4,%5,%6,%7}, {%8,%9}, {%0,%1,%2,%3};"
        : "+f"(c[0]), "+f"(c[1]), "+f"(c[2]), "+f"(c[3])
        : "r"(a[0]), "r"(a[1]), "r"(a[2]), "r"(a[3]), "r"(b0), "r"(b1));
}
// column permutation: p = j*64 + g*16 + uu  <->  gcol = g*1024 + j*16 + uu
__device__ __forceinline__ int gcol_of(int p) {
    return ((p >> 4) & 3) * 1024 + (p >> 6) * 16 + (p & 15);
}
// smem tile: rows of 128B (64 bf16), 16B chunks xor-swizzled by row
__device__ __forceinline__ uint32_t tadr(int row, int ch) {
    return (uint32_t)(row * 128 + ((ch ^ (row & 7)) << 4));
}

// ---------------- init -----------------------------------------------------
__global__ void init_kernel() {
    int i = blockIdx.x * 256 + threadIdx.x;
    uint4 z = make_uint4(0, 0, 0, 0);
    if (i < 8192) { ((uint4*)g_hh[0])[i] = z; ((uint4*)g_hl[0])[i] = z; }
    if (i < 16384) ((uint4*)g_c)[i] = z;
}

// ---------------- packers --------------------------------------------------
__global__ void __launch_bounds__(256) pack_x_kernel(const float* __restrict__ x) {
    int u = blockIdx.x * 256 + threadIdx.x;           // 4194304
    int k8 = u & 127, m = u >> 7;
    int t = m >> 6, b = m & 63;
    const float* s = x + ((size_t)(b * 512 + t)) * 1024 + k8 * 8;
    float4 v0 = *(const float4*)s, v1 = *(const float4*)(s + 4);
    float v[8] = {v0.x, v0.y, v0.z, v0.w, v1.x, v1.y, v1.z, v1.w};
    __nv_bfloat16 hb[8], lb[8];
#pragma unroll
    for (int i = 0; i < 8; i++) {
        hb[i] = __float2bfloat16(v[i]);
        lb[i] = __float2bfloat16(v[i] - __bfloat162float(hb[i]));
    }
    size_t o = (size_t)m * 1024 + k8 * 8;
    *(uint4*)(g_xh + o) = *(uint4*)hb;
    *(uint4*)(g_xl + o) = *(uint4*)lb;
}

// W[k][gcol] -> rows p (permuted), K-contig, via smem transpose
__global__ void __launch_bounds__(256) pack_w_kernel(const float* __restrict__ W, int mode) {
    __shared__ float s[32][33];
    int p0 = blockIdx.x * 32, k0 = blockIdx.y * 32;
    int tid = threadIdx.x;
#pragma unroll
    for (int i = 0; i < 4; i++) {
        int idx = tid + i * 256;
        int kk = idx >> 5, pp = idx & 31;
        s[kk][pp] = W[(size_t)(k0 + kk) * 4096 + gcol_of(p0 + pp)];
    }
    __syncthreads();
    if (tid < 128) {
        int pp = tid >> 2, k8 = (tid & 3) * 8;
        __nv_bfloat16 hb[8], lb[8];
#pragma unroll
        for (int i = 0; i < 8; i++) {
            float v = s[k8 + i][pp];
            hb[i] = __float2bfloat16(v);
            lb[i] = __float2bfloat16(v - __bfloat162float(hb[i]));
        }
        size_t o = (size_t)(p0 + pp) * 1024 + k0 + k8;
        __nv_bfloat16* dh = mode ? g_whh : g_wxh;
        __nv_bfloat16* dl = mode ? g_whl : g_wxl;
        *(uint4*)(dh + o) = *(uint4*)hb;
        *(uint4*)(dl + o) = *(uint4*)lb;
    }
}

// ---------------- x_proj GEMM ---------------------------------------------
// C[m=128 rows (2t x 64b)][n=128 p-cols], K=1024, 2-stage cp.async pipeline.
// smem stage (64KB): Ah(16K) Al(16K) Bh(16K) Bl(16K); 2 stages = 128KB.
__device__ __forceinline__ void xp_load(uint32_t sb, int s, int tid, int m0, int p0, int k0) {
    uint32_t st = sb + s * 65536;
#pragma unroll
    for (int rep = 0; rep < 4; rep++) {
        int c = tid + rep * 256;
        int row = c >> 3, ch = c & 7;
        uint32_t so = tadr(row, ch);
        size_t go = (size_t)k0 + ch * 8;
        cp16(st + so,         g_xh  + (size_t)(m0 + row) * 1024 + go);
        cp16(st + 16384 + so, g_xl  + (size_t)(m0 + row) * 1024 + go);
        cp16(st + 32768 + so, g_wxh + (size_t)(p0 + row) * 1024 + go);
        cp16(st + 49152 + so, g_wxl + (size_t)(p0 + row) * 1024 + go);
    }
}

__device__ __forceinline__ void xp_compute(uint32_t sb, int s, int lane,
                                           int m_off, int n_off, float C[16][4]) {
    uint32_t st = sb + s * 65536;
    int r15 = lane & 15, kh = lane >> 4;
#pragma unroll
    for (int ks = 0; ks < 4; ks++) {
        int ch = ks * 2 + kh;
        uint32_t aH[8], aL[8], bH[16], bL[16];
#pragma unroll
        for (int mt = 0; mt < 2; mt++) {
            uint32_t o = tadr(m_off + mt * 16 + r15, ch);
            ldsm4(aH + mt * 4, st + o);
            ldsm4(aL + mt * 4, st + 16384 + o);
        }
#pragma unroll
        for (int nt = 0; nt < 4; nt++) {
            uint32_t o = tadr(n_off + nt * 16 + r15, ch);
            ldsm4(bH + nt * 4, st + 32768 + o);
            ldsm4(bL + nt * 4, st + 49152 + o);
        }
#pragma unroll
        for (int mt = 0; mt < 2; mt++)
#pragma unroll
            for (int n8 = 0; n8 < 8; n8++) {
                int g = (n8 >> 1) * 4 + (n8 & 1);
                float* cc = C[mt * 8 + n8];
                mma_bf16(cc, aH + mt * 4, bH[g], bH[g + 2]);
                mma_bf16(cc, aH + mt * 4, bL[g], bL[g + 2]);
                mma_bf16(cc, aL + mt * 4, bH[g], bH[g + 2]);
            }
    }
}

__global__ void __launch_bounds__(256, 1) xproj_kernel(const float* __restrict__ bias) {
    extern __shared__ __align__(16) unsigned char sm[];
    uint32_t sb = smem_u32(sm);
    int tid = threadIdx.x, lane = tid & 31, w = tid >> 5;
    int p0 = blockIdx.x * 128, m0 = blockIdx.y * 128;
    int m_off = (w & 3) * 32, n_off = (w >> 2) * 64;

    float C[16][4];
#pragma unroll
    for (int i = 0; i < 16; i++)
#pragma unroll
        for (int q = 0; q < 4; q++) C[i][q] = 0.0f;

    xp_load(sb, 0, tid, m0, p0, 0);  CP_COMMIT();
    xp_load(sb, 1, tid, m0, p0, 64); CP_COMMIT();
#pragma unroll 1
    for (int kt = 0; kt < 16; kt++) {
        if (kt < 15) { CP_WAIT1(); } else { CP_WAIT0(); }
        __syncthreads();
        xp_compute(sb, kt & 1, lane, m_off, n_off, C);
        __syncthreads();
        if (kt + 2 < 16) { xp_load(sb, kt & 1, tid, m0, p0, (kt + 2) * 64); CP_COMMIT(); }
    }

    // epilogue: C -> smem transposed [n][m], then coalesced global write
    float* sC = (float*)sm;  // [128][132]
    int r = lane >> 2, c2 = (lane & 3) * 2;
#pragma unroll
    for (int mt = 0; mt < 2; mt++)
#pragma unroll
        for (int n8 = 0; n8 < 8; n8++) {
            float* cf = C[mt * 8 + n8];
            int m = m_off + mt * 16 + r;
            int n = n_off + n8 * 8 + c2;
            sC[n * 132 + m]           = cf[0];
            sC[(n + 1) * 132 + m]     = cf[1];
            sC[n * 132 + m + 8]       = cf[2];
            sC[(n + 1) * 132 + m + 8] = cf[3];
        }
    __syncthreads();
    {
        int n = tid >> 1, tq = tid & 1;
        int p = p0 + n;
        float bv = bias[gcol_of(p)];
        float* dst = g_xproj + ((size_t)(blockIdx.y * 2 + tq) * 4096 + p) * 64;
        const float* src = sC + n * 132 + tq * 64;
#pragma unroll
        for (int i = 0; i < 16; i++) {
            float4 v = *(const float4*)(src + i * 4);
            v.x += bv; v.y += bv; v.z += bv; v.w += bv;
            *(float4*)(dst + i * 4) = v;
        }
    }
}

// ---------------- step kernel ----------------------------------------------
// 64 CTAs; CTA j: C[64 b][64 p] = h @ Wh_p^T, K=1024; fused gates.
// smem: stages 2x32KB (Ah 8K, Al 8K, Bh 8K, Bl 8K) + Xp 16KB at 65536.
__device__ __forceinline__ void st_load(uint32_t sb, int s, int tid,
                                        const __nv_bfloat16* hh, const __nv_bfloat16* hl,
                                        int p0, int k0) {
    uint32_t st = sb + s * 32768;
#pragma unroll
    for (int rep = 0; rep < 2; rep++) {
        int c = tid + rep * 256;
        int row = c >> 3, ch = c & 7;
        uint32_t so = tadr(row, ch);
        size_t go = (size_t)k0 + ch * 8;
        cp16(st + so,         hh + (size_t)row * 1024 + go);
        cp16(st + 8192 + so,  hl + (size_t)row * 1024 + go);
        cp16(st + 16384 + so, g_whh + (size_t)(p0 + row) * 1024 + go);
        cp16(st + 24576 + so, g_whl + (size_t)(p0 + row) * 1024 + go);
    }
}

__device__ __forceinline__ void st_compute(uint32_t sb, int s, int lane,
                                           int m_off, int n_off, float C[4][4]) {
    uint32_t st = sb + s * 32768;
    int r15 = lane & 15, kh = lane >> 4;
#pragma unroll
    for (int ks = 0; ks < 4; ks++) {
        int ch = ks * 2 + kh;
        uint32_t aH[8], aL[8], bH[4], bL[4];
#pragma unroll
        for (int mt = 0; mt < 2; mt++) {
            uint32_t o = tadr(m_off + mt * 16 + r15, ch);
            ldsm4(aH + mt * 4, st + o);
            ldsm4(aL + mt * 4, st + 8192 + o);
        }
        {
            uint32_t o = tadr(n_off + r15, ch);
            ldsm4(bH, st + 16384 + o);
            ldsm4(bL, st + 24576 + o);
        }
#pragma unroll
        for (int mt = 0; mt < 2; mt++)
#pragma unroll
            for (int nn = 0; nn < 2; nn++) {
                float* cc = C[mt * 2 + nn];
                mma_bf16(cc, aH + mt * 4, bH[nn], bH[nn + 2]);
                mma_bf16(cc, aH + mt * 4, bL[nn], bL[nn + 2]);
                mma_bf16(cc, aL + mt * 4, bH[nn], bH[nn + 2]);
            }
    }
}

__global__ void __launch_bounds__(256, 1) step_kernel(float* __restrict__ y, int t) {
    extern __shared__ __align__(16) unsigned char sm[];
    uint32_t sb = smem_u32(sm);
    int tid = threadIdx.x, lane = tid & 31, w = tid >> 5;
    int j = blockIdx.x, p0 = j * 64;
    int m_off = (w & 1) * 32, n_off = (w >> 1) * 16;
    const __nv_bfloat16* hh = g_hh[t & 1];
    const __nv_bfloat16* hl = g_hl[t & 1];

    float C[4][4];
#pragma unroll
    for (int i = 0; i < 4; i++)
#pragma unroll
        for (int q = 0; q < 4; q++) C[i][q] = 0.0f;

    // x_proj slice for this CTA: 16KB contiguous, overlapped with GEMM
    {
        const char* xpg = (const char*)(g_xproj + ((size_t)t * 4096 + p0) * 64);
#pragma unroll
        for (int rep = 0; rep < 4; rep++) {
            int c = tid + rep * 256;
            cp16(sb + 65536 + c * 16, xpg + c * 16);
        }
    }
    st_load(sb, 0, tid, hh, hl, p0, 0);  CP_COMMIT();
    st_load(sb, 1, tid, hh, hl, p0, 64); CP_COMMIT();
#pragma unroll 1
    for (int kt = 0; kt < 16; kt++) {
        if (kt < 15) { CP_WAIT1(); } else { CP_WAIT0(); }
        __syncthreads();
        st_compute(sb, kt & 1, lane, m_off, n_off, C);
        __syncthreads();
        if (kt + 2 < 16) { st_load(sb, kt & 1, tid, hh, hl, p0, (kt + 2) * 64); CP_COMMIT(); }
    }

    // epilogue: frags -> Zs[n][b], then fused gates
    float* Zs = (float*)sm;                 // [64][66]
    const float* Xp = (const float*)(sm + 65536);  // [64 p][64 b]
    int r = lane >> 2, c2 = (lane & 3) * 2;
#pragma unroll
    for (int mt = 0; mt < 2; mt++)
#pragma unroll
        for (int nn = 0; nn < 2; nn++) {
            float* cf = C[mt * 2 + nn];
            int m = m_off + mt * 16 + r;
            int n = n_off + nn * 8 + c2;
            Zs[n * 66 + m]           = cf[0];
            Zs[(n + 1) * 66 + m]     = cf[1];
            Zs[n * 66 + m + 8]       = cf[2];
            Zs[(n + 1) * 66 + m + 8] = cf[3];
        }
    __syncthreads();
    {
        int b = tid >> 2, uq = tid & 3;
        float hv[4];
#pragma unroll
        for (int v = 0; v < 4; v++) {
            int uu = uq * 4 + v, u = j * 16 + uu;
            float zi = Zs[uu * 66 + b]        + Xp[uu * 64 + b];
            float zf = Zs[(16 + uu) * 66 + b] + Xp[(16 + uu) * 64 + b];
            float zg = Zs[(32 + uu) * 66 + b] + Xp[(32 + uu) * 64 + b];
            float zo = Zs[(48 + uu) * 66 + b] + Xp[(48 + uu) * 64 + b];
            float ig = 1.0f / (1.0f + __expf(-zi));
            float fg = 1.0f / (1.0f + __expf(-zf));
            float gg = 2.0f / (1.0f + __expf(-2.0f * zg)) - 1.0f;
            float og = 1.0f / (1.0f + __expf(-zo));
            float cn = fg * g_c[b * 1024 + u] + ig * gg;
            g_c[b * 1024 + u] = cn;
            float th = 2.0f / (1.0f + __expf(-2.0f * cn)) - 1.0f;
            hv[v] = og * th;
            y[((size_t)b * 512 + t) * 1024 + u] = hv[v];
        }
        __nv_bfloat16 hb[4], lb[4];
#pragma unroll
        for (int v = 0; v < 4; v++) {
            hb[v] = __float2bfloat16(hv[v]);
            lb[v] = __float2bfloat16(hv[v] - __bfloat162float(hb[v]));
        }
        int par = (t + 1) & 1;
        size_t o = (size_t)b * 1024 + j * 16 + uq * 4;
        *(uint2*)(g_hh[par] + o) = *(uint2*)hb;
        *(uint2*)(g_hl[par] + o) = *(uint2*)lb;
    }
}

// ---------------------------------------------------------------------------
extern "C" void kernel_launch(void* const* d_in, const int* in_sizes, int n_in,
                              void* d_out, int out_size)
{
    const float* x  = (const float*)d_in[0];
    const float* Wx = (const float*)d_in[1];
    const float* Wh = (const float*)d_in[2];
    const float* b  = (const float*)d_in[3];
    float* y = (float*)d_out;

    cudaFuncSetAttribute(xproj_kernel, cudaFuncAttributeMaxDynamicSharedMemorySize, 131072);
    cudaFuncSetAttribute(step_kernel,  cudaFuncAttributeMaxDynamicSharedMemorySize, 81920);

    init_kernel<<<64, 256>>>();
    pack_x_kernel<<<16384, 256>>>(x);
    pack_w_kernel<<<dim3(128, 32), 256>>>(Wx, 0);
    pack_w_kernel<<<dim3(128, 32), 256>>>(Wh, 1);
    xproj_kernel<<<dim3(32, 256), 256, 131072>>>(b);
    for (int t = 0; t < 512; t++)
        step_kernel<<<64, 256, 81920>>>(y, t);
}